// round 1
// baseline (speedup 1.0000x reference)
#include <cuda_runtime.h>
#include <math.h>

// ---------------------------------------------------------------------------
// Scratch accumulators (no allocations allowed -> __device__ globals)
// g_acc[0] = raw seg BCE sum
// g_acc[1] = det loss (already weighted: sum over scales/images of per-image
//            (cls_l+reg_l+cen_l) / (3*B))
// g_acc[2] = weighted cls focal loss (0.5 * mean)
// ---------------------------------------------------------------------------
__device__ double g_acc[4];

__global__ void zero_acc_kernel() {
    if (threadIdx.x < 4) g_acc[threadIdx.x] = 0.0;
}

// ---------------------------------------------------------------------------
// Elementwise math helpers
// ---------------------------------------------------------------------------
__device__ __forceinline__ float bce_f(float x, float y) {
    // max(x,0) - x*y + log1p(exp(-|x|))
    return fmaxf(x, 0.0f) - x * y + log1pf(__expf(-fabsf(x)));
}

__device__ __forceinline__ float focal_el(float x, float t) {
    float p   = 1.0f / (1.0f + __expf(-x));
    float ce  = bce_f(x, t);
    float p_t = p * t + (1.0f - p) * (1.0f - t);
    float a_t = 0.25f * t + 0.75f * (1.0f - t);
    float om  = 1.0f - p_t;
    return a_t * om * om * ce;
}

// Block reduction of a single float; result valid on thread 0.
__device__ __forceinline__ float block_reduce(float v, float* sh) {
    int lane = threadIdx.x & 31;
    int wid  = threadIdx.x >> 5;
    #pragma unroll
    for (int o = 16; o; o >>= 1) v += __shfl_down_sync(0xffffffffu, v, o);
    if (lane == 0) sh[wid] = v;
    __syncthreads();
    int nw = (blockDim.x + 31) >> 5;
    v = (threadIdx.x < nw) ? sh[threadIdx.x] : 0.0f;
    if (wid == 0) {
        #pragma unroll
        for (int o = 16; o; o >>= 1) v += __shfl_down_sync(0xffffffffu, v, o);
    }
    __syncthreads();   // allow shared reuse
    return v;
}

// ---------------------------------------------------------------------------
// Segmentation BCE: logits (32,4,512,512) f32, mask (32,512,512) i32 broadcast
// over channel dim. Vectorized float4/int4 grid-stride reduction.
// ---------------------------------------------------------------------------
__global__ void seg_loss_kernel(const float* __restrict__ logits,
                                const int*   __restrict__ mask) {
    const long long HW   = 512LL * 512LL;        // 2^18
    const long long NS   = 32LL * HW;            // spatial elements
    const long long NVEC = NS >> 2;              // 4 spatial per thread-iter

    float acc = 0.0f;
    long long stride = (long long)gridDim.x * blockDim.x;
    for (long long v = (long long)blockIdx.x * blockDim.x + threadIdx.x;
         v < NVEC; v += stride) {
        long long s  = v << 2;
        long long b  = s >> 18;            // HW = 2^18
        long long hw = s & (HW - 1);

        int4 m = *reinterpret_cast<const int4*>(mask + b * HW + hw);
        float y0 = (float)m.x, y1 = (float)m.y, y2 = (float)m.z, y3 = (float)m.w;

        #pragma unroll
        for (int c = 0; c < 4; c++) {
            float4 x = *reinterpret_cast<const float4*>(
                logits + (b * 4 + c) * HW + hw);
            acc += bce_f(x.x, y0);
            acc += bce_f(x.y, y1);
            acc += bce_f(x.z, y2);
            acc += bce_f(x.w, y3);
        }
    }

    __shared__ float sh[32];
    float bs = block_reduce(acc, sh);
    if (threadIdx.x == 0) atomicAdd(&g_acc[0], (double)bs);
}

// ---------------------------------------------------------------------------
// Detection loss for one FPN scale. grid.x = B (one block per image).
// cls: (B,5,H,W) -- channel 0 dropped; reg: (B,4,H,W); cent: (B,1,H,W)
// boxes: (B,20,4) cx,cy,w,h in [0,1] (scaled by 512); labels: (B,20) int
// ---------------------------------------------------------------------------
template <int STRIDE, int HWDIM>
__global__ void det_loss_kernel(const float* __restrict__ cls,
                                const float* __restrict__ reg,
                                const float* __restrict__ cent,
                                const float* __restrict__ boxes,
                                const int*   __restrict__ labels) {
    const int NB = 20;
    const int Wd = HWDIM;
    const int L  = HWDIM * HWDIM;
    const int b  = blockIdx.x;
    const int B  = gridDim.x;

    __shared__ float sx0[NB], sy0[NB], sx1[NB], sy1[NB], sa[NB];
    __shared__ int   slab[NB];
    if (threadIdx.x < NB) {
        int j = threadIdx.x;
        const float* bp = boxes + ((long long)b * NB + j) * 4;
        float cx = bp[0] * 512.0f;
        float cy = bp[1] * 512.0f;
        float w  = bp[2] * 512.0f;
        float h  = bp[3] * 512.0f;
        float x0 = cx - w * 0.5f, y0 = cy - h * 0.5f;
        float x1 = cx + w * 0.5f, y1 = cy + h * 0.5f;
        sx0[j] = x0; sy0[j] = y0; sx1[j] = x1; sy1[j] = y1;
        sa[j]  = (x1 - x0) * (y1 - y0);
        slab[j] = labels[b * NB + j];
    }
    __syncthreads();

    float cls_sum = 0.0f, reg_sum = 0.0f, cen_sum = 0.0f, npos_f = 0.0f;

    const float inv_stride = 1.0f / (float)STRIDE;
    for (int l = threadIdx.x; l < L; l += blockDim.x) {
        int   hh = l / Wd, ww = l - hh * Wd;
        float lx = (ww + 0.5f) * (float)STRIDE;
        float ly = (hh + 0.5f) * (float)STRIDE;

        float best_a = INFINITY;
        int   best   = 0;
        bool  pos    = false;
        #pragma unroll
        for (int j = 0; j < NB; j++) {
            float l_ = lx - sx0[j];
            float t_ = ly - sy0[j];
            float r_ = sx1[j] - lx;
            float m_ = sy1[j] - ly;
            float mn = fminf(fminf(l_, t_), fminf(r_, m_));
            bool ins = mn > 0.0f;
            pos = pos || ins;
            float a = ins ? sa[j] : INFINITY;
            if (a < best_a) { best_a = a; best = j; }   // first-min semantics
        }

        // reg targets (ltrb of argmin box, / stride)
        float rt0 = (lx - sx0[best]) * inv_stride;
        float rt1 = (ly - sy0[best]) * inv_stride;
        float rt2 = (sx1[best] - lx) * inv_stride;
        float rt3 = (sy1[best] - ly) * inv_stride;

        int label = pos ? slab[best] : -1;

        // focal over 4 classes (channels 1..4 of the 5-channel tensor)
        #pragma unroll
        for (int c = 0; c < 4; c++) {
            float x = cls[((long long)b * 5 + (c + 1)) * L + l];
            cls_sum += focal_el(x, (c == label) ? 1.0f : 0.0f);
        }

        if (pos) {
            // smooth-L1, mean over 4 components
            float rt[4] = {rt0, rt1, rt2, rt3};
            float sl1 = 0.0f;
            #pragma unroll
            for (int c = 0; c < 4; c++) {
                float d  = reg[((long long)b * 4 + c) * L + l] - rt[c];
                float ad = fabsf(d);
                sl1 += (ad < 1.0f) ? 0.5f * d * d : ad - 0.5f;
            }
            reg_sum += sl1 * 0.25f;

            // centerness target
            const float eps = 1e-6f;
            float mnlr = fminf(rt0, rt2), mxlr = fmaxf(rt0, rt2);
            float mntb = fminf(rt1, rt3), mxtb = fmaxf(rt1, rt3);
            float v = (mnlr / (mxlr + eps)) * (mntb / (mxtb + eps));
            v = fminf(fmaxf(v, 0.0f), 1.0f);
            float cen_t = sqrtf(v);
            cen_sum += bce_f(cent[(long long)b * L + l], cen_t);
            npos_f  += 1.0f;
        }
    }

    __shared__ float sh[32];
    float cls_tot  = block_reduce(cls_sum, sh);
    float reg_tot  = block_reduce(reg_sum, sh);
    float cen_tot  = block_reduce(cen_sum, sh);
    float npos_tot = block_reduce(npos_f,  sh);

    if (threadIdx.x == 0) {
        float cls_l = cls_tot / (float)(L * 4);
        float reg_l = (npos_tot > 0.0f) ? reg_tot / npos_tot : 0.0f;
        float cen_l = (npos_tot > 0.0f) ? cen_tot / npos_tot : 0.0f;
        double contrib = (double)(cls_l + reg_l + cen_l) / (3.0 * (double)B);
        atomicAdd(&g_acc[1], contrib);
    }
}

// ---------------------------------------------------------------------------
// Classification focal loss: pred (32,10), target (32,)
// ---------------------------------------------------------------------------
__global__ void cls_loss_kernel(const float* __restrict__ pred,
                                const int*   __restrict__ target) {
    const int N = 32 * 10;
    float v = 0.0f;
    int i = threadIdx.x;
    if (i < N) {
        int bb = i / 10, cc = i - bb * 10;
        float t = (target[bb] == cc) ? 1.0f : 0.0f;
        v = focal_el(pred[i], t);
    }
    __shared__ float sh[32];
    float s = block_reduce(v, sh);
    if (threadIdx.x == 0) {
        atomicAdd(&g_acc[2], 0.5 * (double)s / (double)N);   // W_CLS = 0.5
    }
}

// ---------------------------------------------------------------------------
// Final combine
// ---------------------------------------------------------------------------
__global__ void finalize_kernel(float* __restrict__ out, int n) {
    double seg_mean = g_acc[0] / (32.0 * 4.0 * 512.0 * 512.0);
    double total = seg_mean + g_acc[1] + g_acc[2];   // W_SEG=1, W_DET=1
    for (int i = threadIdx.x; i < n; i += blockDim.x)
        out[i] = (float)total;
}

// ---------------------------------------------------------------------------
// Launch
// Input order (metadata): seg_logits, seg_mask, cls_s0, cls_s1, cls_s2,
// reg_s0, reg_s1, reg_s2, cen_s0, cen_s1, cen_s2, boxes, labels, cls_pred,
// cls_target
// ---------------------------------------------------------------------------
extern "C" void kernel_launch(void* const* d_in, const int* in_sizes, int n_in,
                              void* d_out, int out_size) {
    const float* seg_logits = (const float*)d_in[0];
    const int*   seg_mask   = (const int*)  d_in[1];
    const float* cls_s0     = (const float*)d_in[2];
    const float* cls_s1     = (const float*)d_in[3];
    const float* cls_s2     = (const float*)d_in[4];
    const float* reg_s0     = (const float*)d_in[5];
    const float* reg_s1     = (const float*)d_in[6];
    const float* reg_s2     = (const float*)d_in[7];
    const float* cen_s0     = (const float*)d_in[8];
    const float* cen_s1     = (const float*)d_in[9];
    const float* cen_s2     = (const float*)d_in[10];
    const float* boxes      = (const float*)d_in[11];
    const int*   labels     = (const int*)  d_in[12];
    const float* cls_pred   = (const float*)d_in[13];
    const int*   cls_target = (const int*)  d_in[14];
    float* out = (float*)d_out;

    zero_acc_kernel<<<1, 32>>>();

    // Memory-bound bulk pass: 160 MB of reads
    seg_loss_kernel<<<2368, 256>>>(seg_logits, seg_mask);

    det_loss_kernel<8,  64><<<32, 256>>>(cls_s0, reg_s0, cen_s0, boxes, labels);
    det_loss_kernel<16, 32><<<32, 256>>>(cls_s1, reg_s1, cen_s1, boxes, labels);
    det_loss_kernel<32, 16><<<32, 256>>>(cls_s2, reg_s2, cen_s2, boxes, labels);

    cls_loss_kernel<<<1, 320>>>(cls_pred, cls_target);

    finalize_kernel<<<1, 32>>>(out, out_size);
}

// round 2
// speedup vs baseline: 3.4489x; 3.4489x over previous
#include <cuda_runtime.h>
#include <math.h>

// ---------------------------------------------------------------------------
// Scratch accumulators (__device__ globals; allocations are forbidden)
// ---------------------------------------------------------------------------
__device__ double g_seg;            // seg BCE raw sum
__device__ float  g_det[3][32][4];  // per scale/image: cls_sum, reg_sum, cen_sum, npos
__device__ float  g_cls;            // cls focal raw sum

__global__ void zero_acc_kernel() {
    int i = threadIdx.x;
    if (i == 0) { g_seg = 0.0; g_cls = 0.0f; }
    if (i < 3 * 32 * 4) (&g_det[0][0][0])[i] = 0.0f;
}

// ---------------------------------------------------------------------------
// Math helpers: one __expf + one __logf + one fast div per element
//   e   = exp(-|x|)
//   l1p = log(1+e)
//   softplus(x)  = max(x,0)+l1p ;  softplus(-x) = max(-x,0)+l1p
//   sigmoid(x)   = x>=0 ? 1/(1+e) : e/(1+e)
// ---------------------------------------------------------------------------
__device__ __forceinline__ float bce_f(float x, float y) {
    float e = __expf(-fabsf(x));
    return fmaxf(x, 0.0f) - x * y + __logf(1.0f + e);
}

// focal element with binary target t (0/1), alpha=0.25 gamma=2
__device__ __forceinline__ float focal_el(float x, bool t1) {
    float e   = __expf(-fabsf(x));
    float l1p = __logf(1.0f + e);
    float d   = __fdividef(1.0f, 1.0f + e);
    float sig = (x >= 0.0f) ? d : e * d;          // sigmoid(x)
    if (t1) {
        float om = 1.0f - sig;                     // (1-p)
        float sp = fmaxf(-x, 0.0f) + l1p;          // softplus(-x) = bce(x,1)
        return 0.25f * om * om * sp;
    } else {
        float sp = fmaxf(x, 0.0f) + l1p;           // softplus(x) = bce(x,0)
        return 0.75f * sig * sig * sp;
    }
}

// Block reduction; result valid on thread 0.
__device__ __forceinline__ float block_reduce(float v, float* sh) {
    int lane = threadIdx.x & 31;
    int wid  = threadIdx.x >> 5;
    #pragma unroll
    for (int o = 16; o; o >>= 1) v += __shfl_down_sync(0xffffffffu, v, o);
    if (lane == 0) sh[wid] = v;
    __syncthreads();
    int nw = (blockDim.x + 31) >> 5;
    v = (threadIdx.x < nw) ? sh[threadIdx.x] : 0.0f;
    if (wid == 0) {
        #pragma unroll
        for (int o = 16; o; o >>= 1) v += __shfl_down_sync(0xffffffffu, v, o);
    }
    __syncthreads();
    return v;
}

// ---------------------------------------------------------------------------
// Detection chunk: one block handles 256 locations of (scale, image b).
// blockDim.x == 256, so each thread owns exactly one location.
// ---------------------------------------------------------------------------
template <int STRIDE, int HWDIM, int SCALE>
__device__ void det_chunk(int b, int chunk,
                          const float* __restrict__ cls,
                          const float* __restrict__ reg,
                          const float* __restrict__ cent,
                          const float* __restrict__ boxes,
                          const int*   __restrict__ labels,
                          float* sh) {
    const int NB = 20;
    const int L  = HWDIM * HWDIM;

    __shared__ float sx0[NB], sy0[NB], sx1[NB], sy1[NB], sa[NB];
    __shared__ int   slab[NB];
    if (threadIdx.x < NB) {
        int j = threadIdx.x;
        const float* bp = boxes + ((long long)b * NB + j) * 4;
        float cx = bp[0] * 512.0f, cy = bp[1] * 512.0f;
        float w  = bp[2] * 512.0f, h  = bp[3] * 512.0f;
        float x0 = cx - w * 0.5f, y0 = cy - h * 0.5f;
        float x1 = cx + w * 0.5f, y1 = cy + h * 0.5f;
        sx0[j] = x0; sy0[j] = y0; sx1[j] = x1; sy1[j] = y1;
        sa[j]  = (x1 - x0) * (y1 - y0);
        slab[j] = labels[b * NB + j];
    }
    __syncthreads();

    const int l  = chunk * 256 + threadIdx.x;     // location index (< L always)
    const int hh = l / HWDIM, ww = l - hh * HWDIM;
    const float lx = (ww + 0.5f) * (float)STRIDE;
    const float ly = (hh + 0.5f) * (float)STRIDE;
    const float inv_stride = 1.0f / (float)STRIDE;

    float best_a = INFINITY;
    int   best   = 0;
    bool  pos    = false;
    #pragma unroll 5
    for (int j = 0; j < NB; j++) {
        float l_ = lx - sx0[j];
        float t_ = ly - sy0[j];
        float r_ = sx1[j] - lx;
        float m_ = sy1[j] - ly;
        float mn = fminf(fminf(l_, t_), fminf(r_, m_));
        bool ins = mn > 0.0f;
        pos = pos || ins;
        float a = ins ? sa[j] : INFINITY;
        if (a < best_a) { best_a = a; best = j; }  // strict < = first-min
    }

    float rt0 = (lx - sx0[best]) * inv_stride;
    float rt1 = (ly - sy0[best]) * inv_stride;
    float rt2 = (sx1[best] - lx) * inv_stride;
    float rt3 = (sy1[best] - ly) * inv_stride;
    int label = pos ? slab[best] : -1;

    float cls_sum = 0.0f;
    #pragma unroll
    for (int c = 0; c < 4; c++) {
        float x = cls[((long long)b * 5 + (c + 1)) * L + l];
        cls_sum += focal_el(x, c == label);
    }

    float reg_sum = 0.0f, cen_sum = 0.0f, npos_f = 0.0f;
    if (pos) {
        float rt[4] = {rt0, rt1, rt2, rt3};
        float sl1 = 0.0f;
        #pragma unroll
        for (int c = 0; c < 4; c++) {
            float d  = reg[((long long)b * 4 + c) * L + l] - rt[c];
            float ad = fabsf(d);
            sl1 += (ad < 1.0f) ? 0.5f * d * d : ad - 0.5f;
        }
        reg_sum = sl1 * 0.25f;

        const float eps = 1e-6f;
        float mnlr = fminf(rt0, rt2), mxlr = fmaxf(rt0, rt2);
        float mntb = fminf(rt1, rt3), mxtb = fmaxf(rt1, rt3);
        float v = __fdividef(mnlr, mxlr + eps) * __fdividef(mntb, mxtb + eps);
        v = fminf(fmaxf(v, 0.0f), 1.0f);
        cen_sum = bce_f(cent[(long long)b * L + l], sqrtf(v));
        npos_f  = 1.0f;
    }

    float ct = block_reduce(cls_sum, sh);
    float rt_ = block_reduce(reg_sum, sh);
    float ce = block_reduce(cen_sum, sh);
    float np = block_reduce(npos_f,  sh);
    if (threadIdx.x == 0) {
        atomicAdd(&g_det[SCALE][b][0], ct);
        atomicAdd(&g_det[SCALE][b][1], rt_);
        atomicAdd(&g_det[SCALE][b][2], ce);
        atomicAdd(&g_det[SCALE][b][3], np);
    }
}

// ---------------------------------------------------------------------------
// Fused main kernel: det blocks first (latency-bound, start early), then the
// single cls block, then seg blocks (memory-bound bulk).
// ---------------------------------------------------------------------------
// Block layout:
//   [0, 512)        det scale0 : b = bid>>4, chunk = bid&15   (64x64 = 16 chunks)
//   [512, 640)      det scale1 : b = x>>2,  chunk = x&3       (32x32 = 4 chunks)
//   [640, 672)      det scale2 : b = x,     chunk = 0         (16x16 = 1 chunk)
//   672             cls focal
//   [673, 673+NSEG) seg grid-stride
static const int DET0_B = 512, DET1_B = 128, DET2_B = 32;
static const int CLS_BID = DET0_B + DET1_B + DET2_B;   // 672
static const int NSEG = 1376;
static const int TOTAL_BLOCKS = CLS_BID + 1 + NSEG;    // 2049

__global__ void __launch_bounds__(256, 3)
main_kernel(const float* __restrict__ seg_logits,
            const int*   __restrict__ seg_mask,
            const float* __restrict__ cls_s0,
            const float* __restrict__ cls_s1,
            const float* __restrict__ cls_s2,
            const float* __restrict__ reg_s0,
            const float* __restrict__ reg_s1,
            const float* __restrict__ reg_s2,
            const float* __restrict__ cen_s0,
            const float* __restrict__ cen_s1,
            const float* __restrict__ cen_s2,
            const float* __restrict__ boxes,
            const int*   __restrict__ labels,
            const float* __restrict__ cls_pred,
            const int*   __restrict__ cls_target) {
    __shared__ float sh[32];
    int bid = blockIdx.x;

    if (bid < DET0_B) {
        det_chunk<8, 64, 0>(bid >> 4, bid & 15, cls_s0, reg_s0, cen_s0, boxes, labels, sh);
        return;
    }
    if (bid < DET0_B + DET1_B) {
        int x = bid - DET0_B;
        det_chunk<16, 32, 1>(x >> 2, x & 3, cls_s1, reg_s1, cen_s1, boxes, labels, sh);
        return;
    }
    if (bid < CLS_BID) {
        int x = bid - DET0_B - DET1_B;
        det_chunk<32, 16, 2>(x, 0, cls_s2, reg_s2, cen_s2, boxes, labels, sh);
        return;
    }
    if (bid == CLS_BID) {
        // cls focal: (32,10) pred, (32,) target — 320 elements
        float v = 0.0f;
        for (int i = threadIdx.x; i < 320; i += blockDim.x) {
            int bb = i / 10, cc = i - bb * 10;
            v += focal_el(cls_pred[i], cls_target[bb] == cc);
        }
        float s = block_reduce(v, sh);
        if (threadIdx.x == 0) atomicAdd(&g_cls, s);
        return;
    }

    // ---- segmentation BCE: (32,4,512,512) logits vs broadcast int mask ----
    const long long HW   = 512LL * 512LL;         // 2^18
    const long long NVEC = (32LL * HW) >> 2;      // float4 groups of spatial
    long long stride = (long long)NSEG * blockDim.x;
    float acc = 0.0f;
    for (long long v = (long long)(bid - CLS_BID - 1) * blockDim.x + threadIdx.x;
         v < NVEC; v += stride) {
        long long s  = v << 2;
        long long b  = s >> 18;
        long long hw = s & (HW - 1);

        int4 m = *reinterpret_cast<const int4*>(seg_mask + b * HW + hw);
        float y0 = (float)m.x, y1 = (float)m.y, y2 = (float)m.z, y3 = (float)m.w;

        #pragma unroll
        for (int c = 0; c < 4; c++) {
            float4 x = *reinterpret_cast<const float4*>(
                seg_logits + (b * 4 + c) * HW + hw);
            acc += bce_f(x.x, y0);
            acc += bce_f(x.y, y1);
            acc += bce_f(x.z, y2);
            acc += bce_f(x.w, y3);
        }
    }
    float bs = block_reduce(acc, sh);
    if (threadIdx.x == 0) atomicAdd(&g_seg, (double)bs);
}

// ---------------------------------------------------------------------------
// Finalize: combine per-image det partials + seg + cls into the scalar.
// ---------------------------------------------------------------------------
__global__ void finalize_kernel(float* __restrict__ out, int n) {
    __shared__ float sh[32];
    int i = threadIdx.x;        // blockDim.x = 128
    float v = 0.0f;
    if (i < 96) {
        int s = i >> 5, b = i & 31;
        const int Ls = (s == 0) ? 4096 : (s == 1) ? 1024 : 256;
        float cls_sum = g_det[s][b][0];
        float reg_sum = g_det[s][b][1];
        float cen_sum = g_det[s][b][2];
        float np      = g_det[s][b][3];
        float cls_l = cls_sum / (float)(Ls * 4);
        float reg_l = (np > 0.0f) ? reg_sum / np : 0.0f;
        float cen_l = (np > 0.0f) ? cen_sum / np : 0.0f;
        v = cls_l + reg_l + cen_l;
    }
    float det_tot = block_reduce(v, sh);
    if (i == 0) {
        double total = g_seg / (32.0 * 4.0 * 512.0 * 512.0)
                     + (double)det_tot / (3.0 * 32.0)
                     + 0.5 * (double)g_cls / 320.0;
        sh[0] = (float)total;
    }
    __syncthreads();
    for (int k = i; k < n; k += blockDim.x) out[k] = sh[0];
}

// ---------------------------------------------------------------------------
// Launch
// ---------------------------------------------------------------------------
extern "C" void kernel_launch(void* const* d_in, const int* in_sizes, int n_in,
                              void* d_out, int out_size) {
    zero_acc_kernel<<<1, 512>>>();

    main_kernel<<<TOTAL_BLOCKS, 256>>>(
        (const float*)d_in[0],  (const int*)d_in[1],
        (const float*)d_in[2],  (const float*)d_in[3],  (const float*)d_in[4],
        (const float*)d_in[5],  (const float*)d_in[6],  (const float*)d_in[7],
        (const float*)d_in[8],  (const float*)d_in[9],  (const float*)d_in[10],
        (const float*)d_in[11], (const int*)d_in[12],
        (const float*)d_in[13], (const int*)d_in[14]);

    finalize_kernel<<<1, 128>>>((float*)d_out, out_size);
}